// round 1
// baseline (speedup 1.0000x reference)
#include <cuda_runtime.h>
#include <cstdint>

#define N_TOT 32768
#define DIM   64
#define KCODES 1024
#define BM    128
#define NTHR  256
#define NCHUNK 16   // K / 64

// output offsets (float32 elements), concatenated in reference return order
#define O_QV   0           // [32,64,32,32] = 2097152
#define O_IDX  2097152     // [32,1,32,32]  = 32768
#define O_LOSS 2129920     // scalar
#define O_EMB  2129921     // [1024,64]
#define O_CL   2195457     // [1024]
#define O_EMA  2196481     // [1024,64]

// scratch (allocation-free rule: __device__ globals)
__device__ float g_dw[KCODES * DIM];
__device__ float g_ni[KCODES];
__device__ float g_ee[KCODES];
__device__ float g_loss;

// ---------------------------------------------------------------------------
// Kernel 0: zero scratch, precompute ||e_k||^2
// ---------------------------------------------------------------------------
__global__ void k_init(const float* __restrict__ emb) {
    int t = blockIdx.x * blockDim.x + threadIdx.x;
    if (t < KCODES * DIM) g_dw[t] = 0.0f;
    if (t < KCODES) {
        g_ni[t] = 0.0f;
        const float4* e4 = reinterpret_cast<const float4*>(emb + (size_t)t * DIM);
        float s = 0.0f;
#pragma unroll
        for (int i = 0; i < 16; i++) {
            float4 v = e4[i];
            s += v.x * v.x + v.y * v.y + v.z * v.z + v.w * v.w;
        }
        g_ee[t] = s;
    }
    if (t == 0) g_loss = 0.0f;
}

// ---------------------------------------------------------------------------
// Kernel 1: distances + argmin + fused epilogue
//   block handles 128 rows; thread (tx,ty) = (tid&15, tid>>4) computes an
//   8-row x 4-code dot micro-tile per 64-code chunk using packed f32x2 FMA.
// ---------------------------------------------------------------------------
__global__ __launch_bounds__(NTHR)
void k_main(const float* __restrict__ z, const float* __restrict__ emb,
            float* __restrict__ out) {
    __shared__ __align__(16) unsigned char sm[49152];
    float* zs = reinterpret_cast<float*>(sm);            // [64][128] = 32KB, zs[d*128+m]
    float* es = reinterpret_cast<float*>(sm + 32768);    // [64][64]  = 16KB, es[d*64+k]
    unsigned long long* smin = reinterpret_cast<unsigned long long*>(sm + 32768); // alias es
    int*   sidx = reinterpret_cast<int*>(sm + 32768 + BM * 8);                    // after smin
    float* lred = reinterpret_cast<float*>(sm);          // alias zs (used only at very end)

    const int tid = threadIdx.x;
    const int tx  = tid & 15;
    const int ty  = tid >> 4;
    const int row0 = blockIdx.x * BM;

    // ---- load z tile, transposed to zs[d][m]. Lane decomposition keeps global
    // reads warp-coalesced (32B-granular) and shared stores <=2-way conflicted.
    for (int i = tid; i < BM * 16; i += NTHR) {       // BM rows * 16 float4 along D
        int m  = (i & 15) | ((i >> 8) << 4);          // 0..127
        int dq = (i >> 4) & 15;                       // 0..15
        float4 v = *reinterpret_cast<const float4*>(z + (size_t)(row0 + m) * DIM + dq * 4);
        zs[(dq * 4 + 0) * BM + m] = v.x;
        zs[(dq * 4 + 1) * BM + m] = v.y;
        zs[(dq * 4 + 2) * BM + m] = v.z;
        zs[(dq * 4 + 3) * BM + m] = v.w;
    }

    float    best[8];
    unsigned bidx[8];
#pragma unroll
    for (int r = 0; r < 8; r++) { best[r] = 3.4e38f; bidx[r] = 0u; }

    for (int c = 0; c < NCHUNK; c++) {
        const int k0 = c * 64;
        __syncthreads();
        // load e chunk transposed to es[d][kk]
        for (int i = tid; i < 64 * 16; i += NTHR) {   // 64 rows * 16 float4
            int kk = (i & 15) | ((i >> 8) << 4);      // 0..63
            int dq = (i >> 4) & 15;
            float4 v = *reinterpret_cast<const float4*>(emb + (size_t)(k0 + kk) * DIM + dq * 4);
            es[(dq * 4 + 0) * 64 + kk] = v.x;
            es[(dq * 4 + 1) * 64 + kk] = v.y;
            es[(dq * 4 + 2) * 64 + kk] = v.z;
            es[(dq * 4 + 3) * 64 + kk] = v.w;
        }
        __syncthreads();

        unsigned long long acc[8][2];
#pragma unroll
        for (int r = 0; r < 8; r++) { acc[r][0] = 0ULL; acc[r][1] = 0ULL; }

#pragma unroll 16
        for (int d = 0; d < DIM; d++) {
            float4 za = *reinterpret_cast<const float4*>(&zs[d * BM + ty * 8]);
            float4 zb = *reinterpret_cast<const float4*>(&zs[d * BM + ty * 8 + 4]);
            float4 ef = *reinterpret_cast<const float4*>(&es[d * 64 + tx * 4]);
            unsigned long long e01, e23;
            asm("mov.b64 %0, {%1,%2};" : "=l"(e01) : "f"(ef.x), "f"(ef.y));
            asm("mov.b64 %0, {%1,%2};" : "=l"(e23) : "f"(ef.z), "f"(ef.w));
            float zr[8] = {za.x, za.y, za.z, za.w, zb.x, zb.y, zb.z, zb.w};
#pragma unroll
            for (int r = 0; r < 8; r++) {
                unsigned long long zd;
                asm("mov.b64 %0, {%1,%1};" : "=l"(zd) : "f"(zr[r]));
                asm("fma.rn.f32x2 %0, %1, %2, %0;" : "+l"(acc[r][0]) : "l"(zd), "l"(e01));
                asm("fma.rn.f32x2 %0, %1, %2, %0;" : "+l"(acc[r][1]) : "l"(zd), "l"(e23));
            }
        }

        // chunk epilogue: dist_key = ||e||^2 - 2*dot  (same ordering as full dist)
        float eek[4];
#pragma unroll
        for (int j = 0; j < 4; j++) eek[j] = __ldg(&g_ee[k0 + tx * 4 + j]);
#pragma unroll
        for (int r = 0; r < 8; r++) {
            float d0, d1, d2, d3;
            asm("mov.b64 {%0,%1}, %2;" : "=f"(d0), "=f"(d1) : "l"(acc[r][0]));
            asm("mov.b64 {%0,%1}, %2;" : "=f"(d2), "=f"(d3) : "l"(acc[r][1]));
            float dd[4] = {d0, d1, d2, d3};
#pragma unroll
            for (int j = 0; j < 4; j++) {
                float dist = fmaf(-2.0f, dd[j], eek[j]);
                if (dist < best[r]) { best[r] = dist; bidx[r] = (unsigned)(k0 + tx * 4 + j); }
            }
        }
    }

    // ---- cross-thread argmin reduce per row (packed key, low-index tiebreak)
    __syncthreads();                 // es region now reusable as smin/sidx
    if (tid < BM) smin[tid] = 0xFFFFFFFFFFFFFFFFULL;
    __syncthreads();
#pragma unroll
    for (int r = 0; r < 8; r++) {
        unsigned u = __float_as_uint(best[r]);
        u = (u & 0x80000000u) ? ~u : (u | 0x80000000u);   // monotonic float->uint
        unsigned long long key = ((unsigned long long)u << 32) | (unsigned long long)bidx[r];
        atomicMin(&smin[ty * 8 + r], key);
    }
    __syncthreads();

    if (tid < BM) {
        int idx = (int)(smin[tid] & 0xFFFFFFFFull);
        sidx[tid] = idx;
        int row = row0 + tid;
        out[O_IDX + row] = (float)idx;
        atomicAdd(&g_ni[idx], 1.0f);
    }
    __syncthreads();

    // ---- fused epilogue: quantized gather + transposed write + loss + dw scatter
    float lacc = 0.0f;
    for (int i = tid; i < BM * DIM; i += NTHR) {
        int m = i & (BM - 1);
        int d = i >> 7;
        int row = row0 + m;
        int idx = sidx[m];
        float zv = zs[d * BM + m];
        float q  = __ldg(&emb[(size_t)idx * DIM + d]);
        float diff = q - zv;
        lacc += diff * diff;
        int b  = row >> 10;
        int hw = row & 1023;
        out[O_QV + (((size_t)(b * DIM + d)) << 10) + hw] = zv + diff;  // straight-through == quantized
        atomicAdd(&g_dw[idx * DIM + d], zv);
    }

    // block loss reduce (reuse zs region — all zs reads are done)
#pragma unroll
    for (int o = 16; o > 0; o >>= 1) lacc += __shfl_xor_sync(0xFFFFFFFFu, lacc, o);
    __syncthreads();
    if ((tid & 31) == 0) lred[tid >> 5] = lacc;
    __syncthreads();
    if (tid == 0) {
        float s = 0.0f;
#pragma unroll
        for (int w = 0; w < NTHR / 32; w++) s += lred[w];
        atomicAdd(&g_loss, s);
    }
}

// ---------------------------------------------------------------------------
// Kernel 2: EMA finalize (1 block, 1024 threads: one thread per code)
// ---------------------------------------------------------------------------
__global__ __launch_bounds__(1024)
void k_final(const float* __restrict__ cs, const float* __restrict__ ema,
             float* __restrict__ out) {
    __shared__ float red[32];
    int k = threadIdx.x;
    float raw = cs[k] * 0.99f + g_ni[k] * 0.01f;
    float s = raw;
#pragma unroll
    for (int o = 16; o > 0; o >>= 1) s += __shfl_xor_sync(0xFFFFFFFFu, s, o);
    if ((k & 31) == 0) red[k >> 5] = s;
    __syncthreads();
    float n = 0.0f;
#pragma unroll
    for (int i = 0; i < 32; i++) n += red[i];
    float smooth = (raw + 1e-5f) / (n + 1024.0f * 1e-5f) * n;
    out[O_CL + k] = smooth;
#pragma unroll
    for (int d = 0; d < DIM; d++) {
        float ne = ema[k * DIM + d] * 0.99f + g_dw[k * DIM + d] * 0.01f;
        out[O_EMA + k * DIM + d] = ne;
        out[O_EMB + k * DIM + d] = ne / smooth;
    }
    if (k == 0) out[O_LOSS] = 0.25f * g_loss / 2097152.0f;
}

// ---------------------------------------------------------------------------
extern "C" void kernel_launch(void* const* d_in, const int* in_sizes, int n_in,
                              void* d_out, int out_size) {
    const float* z   = (const float*)d_in[0];
    const float* emb = (const float*)d_in[1];
    const float* cs  = (const float*)d_in[2];
    const float* ema = (const float*)d_in[3];
    float* out = (float*)d_out;

    k_init<<<256, 256>>>(emb);
    k_main<<<N_TOT / BM, NTHR>>>(z, emb, out);
    k_final<<<1, 1024>>>(cs, ema, out);
}

// round 2
// speedup vs baseline: 2.1708x; 2.1708x over previous
#include <cuda_runtime.h>
#include <cstdint>

#define N_TOT 32768
#define DIM   64
#define KCODES 1024
#define BM    128
#define NTHR  256
#define NCHUNK 16   // K / 64

// output offsets (float32 elements), concatenated in reference return order
#define O_QV   0           // [32,64,32,32] = 2097152
#define O_IDX  2097152     // [32,1,32,32]  = 32768
#define O_LOSS 2129920     // scalar
#define O_EMB  2129921     // [1024,64]
#define O_CL   2195457     // [1024]
#define O_EMA  2196481     // [1024,64]

typedef unsigned long long u64;

// scratch (allocation-free rule: __device__ globals)
__device__ float g_dw[KCODES * DIM];
__device__ float g_ni[KCODES];   // counts, then reused for smoothed cluster size
__device__ float g_ee[KCODES];
__device__ float g_loss;

__device__ __forceinline__ u64 dup_f(float a) {
    u64 r; asm("mov.b64 %0, {%1,%1};" : "=l"(r) : "f"(a)); return r;
}
__device__ __forceinline__ u64 pk(float a, float b) {
    u64 r; asm("mov.b64 %0, {%1,%2};" : "=l"(r) : "f"(a), "f"(b)); return r;
}
__device__ __forceinline__ void fma2(u64& acc, u64 a, u64 b) {
    asm("fma.rn.f32x2 %0, %1, %2, %0;" : "+l"(acc) : "l"(a), "l"(b));
}
__device__ __forceinline__ void unpk(u64 v, float& lo, float& hi) {
    asm("mov.b64 {%0,%1}, %2;" : "=f"(lo), "=f"(hi) : "l"(v));
}

// ---------------------------------------------------------------------------
// Kernel 0: zero scratch, precompute ||e_k||^2
// ---------------------------------------------------------------------------
__global__ void k_init(const float* __restrict__ emb) {
    int t = blockIdx.x * blockDim.x + threadIdx.x;   // 16384 threads
    // zero g_dw with float4 (65536 floats = 16384 float4)
    reinterpret_cast<float4*>(g_dw)[t] = make_float4(0.f, 0.f, 0.f, 0.f);
    if (t < KCODES) {
        g_ni[t] = 0.0f;
        const float4* e4 = reinterpret_cast<const float4*>(emb + (size_t)t * DIM);
        float s = 0.0f;
#pragma unroll
        for (int i = 0; i < 16; i++) {
            float4 v = e4[i];
            s += v.x * v.x + v.y * v.y + v.z * v.z + v.w * v.w;
        }
        g_ee[t] = s;
    }
    if (t == 0) g_loss = 0.0f;
}

// ---------------------------------------------------------------------------
// Kernel 1: distances + argmin + fused epilogue
//   Thread (tx,ty)=(tid&15,tid>>4): 8-row x 4-code tile per 64-code chunk.
//   f32x2 packing along the ROW axis: row pairs are adjacent in zs[d][m], so
//   the float4 shared load already delivers aligned register pairs (no movs).
//   Only 4 e-duplications per d-step.
// ---------------------------------------------------------------------------
__global__ __launch_bounds__(NTHR)
void k_main(const float* __restrict__ z, const float* __restrict__ emb,
            float* __restrict__ out) {
    __shared__ __align__(16) unsigned char sm[49152];
    float* zs = reinterpret_cast<float*>(sm);            // [64][128] zs[d*128+m]
    float* es = reinterpret_cast<float*>(sm + 32768);    // [64][64]  es[d*64+k]
    u64*   smin = reinterpret_cast<u64*>(sm + 32768);    // alias es (after mainloop)
    int*   sidx = reinterpret_cast<int*>(sm + 32768 + BM * 8);
    float* lred = reinterpret_cast<float*>(sm);          // alias zs (very end)

    const int tid = threadIdx.x;
    const int tx  = tid & 15;
    const int ty  = tid >> 4;
    const int row0 = blockIdx.x * BM;

    // ---- load z tile transposed to zs[d][m]
    for (int i = tid; i < BM * 16; i += NTHR) {
        int m  = (i & 15) | ((i >> 8) << 4);
        int dq = (i >> 4) & 15;
        float4 v = *reinterpret_cast<const float4*>(z + (size_t)(row0 + m) * DIM + dq * 4);
        zs[(dq * 4 + 0) * BM + m] = v.x;
        zs[(dq * 4 + 1) * BM + m] = v.y;
        zs[(dq * 4 + 2) * BM + m] = v.z;
        zs[(dq * 4 + 3) * BM + m] = v.w;
    }

    float    best[8];
    unsigned bidx[8];
#pragma unroll
    for (int r = 0; r < 8; r++) { best[r] = 3.4e38f; bidx[r] = 0u; }

    for (int c = 0; c < NCHUNK; c++) {
        const int k0 = c * 64;
        __syncthreads();
        for (int i = tid; i < 64 * 16; i += NTHR) {
            int kk = (i & 15) | ((i >> 8) << 4);
            int dq = (i >> 4) & 15;
            float4 v = *reinterpret_cast<const float4*>(emb + (size_t)(k0 + kk) * DIM + dq * 4);
            es[(dq * 4 + 0) * 64 + kk] = v.x;
            es[(dq * 4 + 1) * 64 + kk] = v.y;
            es[(dq * 4 + 2) * 64 + kk] = v.z;
            es[(dq * 4 + 3) * 64 + kk] = v.w;
        }
        __syncthreads();

        // acc[j*4+p]: code tx*4+j, row pair (ty*8+2p, ty*8+2p+1)
        u64 acc[16];
#pragma unroll
        for (int i = 0; i < 16; i++) acc[i] = 0ULL;

        const float* zp_base = zs + ty * 8;
        const float* ep_base = es + tx * 4;
#pragma unroll 4
        for (int d = 0; d < DIM; d++) {
            float4 za = *reinterpret_cast<const float4*>(zp_base + d * BM);
            float4 zb = *reinterpret_cast<const float4*>(zp_base + d * BM + 4);
            float4 ef = *reinterpret_cast<const float4*>(ep_base + d * 64);
            u64 zp0 = pk(za.x, za.y), zp1 = pk(za.z, za.w);
            u64 zp2 = pk(zb.x, zb.y), zp3 = pk(zb.z, zb.w);
            u64 e0 = dup_f(ef.x), e1 = dup_f(ef.y), e2 = dup_f(ef.z), e3 = dup_f(ef.w);
            fma2(acc[0],  zp0, e0); fma2(acc[1],  zp1, e0);
            fma2(acc[2],  zp2, e0); fma2(acc[3],  zp3, e0);
            fma2(acc[4],  zp0, e1); fma2(acc[5],  zp1, e1);
            fma2(acc[6],  zp2, e1); fma2(acc[7],  zp3, e1);
            fma2(acc[8],  zp0, e2); fma2(acc[9],  zp1, e2);
            fma2(acc[10], zp2, e2); fma2(acc[11], zp3, e2);
            fma2(acc[12], zp0, e3); fma2(acc[13], zp1, e3);
            fma2(acc[14], zp2, e3); fma2(acc[15], zp3, e3);
        }

        // chunk epilogue: dist = ||e||^2 - 2*dot
        float eek[4];
#pragma unroll
        for (int j = 0; j < 4; j++) eek[j] = __ldg(&g_ee[k0 + tx * 4 + j]);
#pragma unroll
        for (int j = 0; j < 4; j++) {
#pragma unroll
            for (int p = 0; p < 4; p++) {
                float d0, d1;
                unpk(acc[j * 4 + p], d0, d1);
                float dist0 = fmaf(-2.0f, d0, eek[j]);
                float dist1 = fmaf(-2.0f, d1, eek[j]);
                unsigned kj = (unsigned)(k0 + tx * 4 + j);
                if (dist0 < best[2 * p])     { best[2 * p]     = dist0; bidx[2 * p]     = kj; }
                if (dist1 < best[2 * p + 1]) { best[2 * p + 1] = dist1; bidx[2 * p + 1] = kj; }
            }
        }
    }

    // ---- cross-thread argmin reduce per row (packed key, low-index tiebreak)
    __syncthreads();
    if (tid < BM) smin[tid] = 0xFFFFFFFFFFFFFFFFULL;
    __syncthreads();
#pragma unroll
    for (int r = 0; r < 8; r++) {
        unsigned u = __float_as_uint(best[r]);
        u = (u & 0x80000000u) ? ~u : (u | 0x80000000u);
        u64 key = ((u64)u << 32) | (u64)bidx[r];
        atomicMin(&smin[ty * 8 + r], key);
    }
    __syncthreads();

    if (tid < BM) {
        int idx = (int)(smin[tid] & 0xFFFFFFFFull);
        sidx[tid] = idx;
        int row = row0 + tid;
        out[O_IDX + row] = (float)idx;
        atomicAdd(&g_ni[idx], 1.0f);
    }
    __syncthreads();

    // ---- fused epilogue: quantized gather + transposed write + loss + dw scatter
    float lacc = 0.0f;
    for (int i = tid; i < BM * DIM; i += NTHR) {
        int m = i & (BM - 1);
        int d = i >> 7;
        int row = row0 + m;
        int idx = sidx[m];
        float zv = zs[d * BM + m];
        float q  = __ldg(&emb[(size_t)idx * DIM + d]);
        float diff = q - zv;
        lacc += diff * diff;
        int b  = row >> 10;
        int hw = row & 1023;
        out[O_QV + (((size_t)(b * DIM + d)) << 10) + hw] = zv + diff;
        atomicAdd(&g_dw[idx * DIM + d], zv);
    }

#pragma unroll
    for (int o = 16; o > 0; o >>= 1) lacc += __shfl_xor_sync(0xFFFFFFFFu, lacc, o);
    __syncthreads();
    if ((tid & 31) == 0) lred[tid >> 5] = lacc;
    __syncthreads();
    if (tid == 0) {
        float s = 0.0f;
#pragma unroll
        for (int w = 0; w < NTHR / 32; w++) s += lred[w];
        atomicAdd(&g_loss, s);
    }
}

// ---------------------------------------------------------------------------
// Kernel 2a: smoothed cluster sizes (1 block) + loss scalar
// ---------------------------------------------------------------------------
__global__ __launch_bounds__(1024)
void k_final_a(const float* __restrict__ cs, float* __restrict__ out) {
    __shared__ float red[32];
    int k = threadIdx.x;
    float raw = cs[k] * 0.99f + g_ni[k] * 0.01f;
    float s = raw;
#pragma unroll
    for (int o = 16; o > 0; o >>= 1) s += __shfl_xor_sync(0xFFFFFFFFu, s, o);
    if ((k & 31) == 0) red[k >> 5] = s;
    __syncthreads();
    float n = 0.0f;
#pragma unroll
    for (int i = 0; i < 32; i++) n += red[i];
    float smooth = (raw + 1e-5f) / (n + 1024.0f * 1e-5f) * n;
    out[O_CL + k] = smooth;
    g_ni[k] = smooth;   // reuse as smoothed size for k_final_b
    if (k == 0) out[O_LOSS] = 0.25f * g_loss / 2097152.0f;
}

// ---------------------------------------------------------------------------
// Kernel 2b: EMA + new embeddings, chip-wide (K*D = 65536 threads)
// ---------------------------------------------------------------------------
__global__ __launch_bounds__(256)
void k_final_b(const float* __restrict__ ema, float* __restrict__ out) {
    int i = blockIdx.x * blockDim.x + threadIdx.x;    // < 65536
    int k = i >> 6;
    float ne = ema[i] * 0.99f + g_dw[i] * 0.01f;
    out[O_EMA + i] = ne;
    out[O_EMB + i] = ne / g_ni[k];
}

// ---------------------------------------------------------------------------
extern "C" void kernel_launch(void* const* d_in, const int* in_sizes, int n_in,
                              void* d_out, int out_size) {
    const float* z   = (const float*)d_in[0];
    const float* emb = (const float*)d_in[1];
    const float* cs  = (const float*)d_in[2];
    const float* ema = (const float*)d_in[3];
    float* out = (float*)d_out;

    k_init<<<64, 256>>>(emb);
    k_main<<<N_TOT / BM, NTHR>>>(z, emb, out);
    k_final_a<<<1, 1024>>>(cs, out);
    k_final_b<<<256, 256>>>(ema, out);
}

// round 4
// speedup vs baseline: 2.3589x; 1.0866x over previous
#include <cuda_runtime.h>
#include <cstdint>

#define N_TOT 32768
#define DIM   64
#define KCODES 1024
#define BM    128
#define NTHR  256
#define NCHUNK 16   // K / 64

// output offsets (float32 elements), concatenated in reference return order
#define O_QV   0           // [32,64,32,32] = 2097152
#define O_IDX  2097152     // [32,1,32,32]  = 32768
#define O_LOSS 2129920     // scalar
#define O_EMB  2129921     // [1024,64]  (ODD offset -> no vector stores!)
#define O_CL   2195457     // [1024]
#define O_EMA  2196481     // [1024,64]  (ODD offset -> no vector stores!)

typedef unsigned long long u64;

// scratch (allocation-free rule: __device__ globals)
__device__ float g_dw[KCODES * DIM];
__device__ float g_ni[KCODES];
__device__ float g_ee[KCODES];
__device__ float g_loss;

__device__ __forceinline__ u64 dup_f(float a) {
    u64 r; asm("mov.b64 %0, {%1,%1};" : "=l"(r) : "f"(a)); return r;
}
__device__ __forceinline__ u64 pk(float a, float b) {
    u64 r; asm("mov.b64 %0, {%1,%2};" : "=l"(r) : "f"(a), "f"(b)); return r;
}
__device__ __forceinline__ void fma2(u64& acc, u64 a, u64 b) {
    asm("fma.rn.f32x2 %0, %1, %2, %0;" : "+l"(acc) : "l"(a), "l"(b));
}
__device__ __forceinline__ void unpk(u64 v, float& lo, float& hi) {
    asm("mov.b64 {%0,%1}, %2;" : "=f"(lo), "=f"(hi) : "l"(v));
}

// ---------------------------------------------------------------------------
// Kernel 0: zero scratch, precompute ||e_k||^2
// ---------------------------------------------------------------------------
__global__ void k_init(const float* __restrict__ emb) {
    int t = blockIdx.x * blockDim.x + threadIdx.x;   // 16384 threads
    reinterpret_cast<float4*>(g_dw)[t] = make_float4(0.f, 0.f, 0.f, 0.f);
    if (t < KCODES) {
        g_ni[t] = 0.0f;
        const float4* e4 = reinterpret_cast<const float4*>(emb + (size_t)t * DIM);
        float s = 0.0f;
#pragma unroll
        for (int i = 0; i < 16; i++) {
            float4 v = e4[i];
            s += v.x * v.x + v.y * v.y + v.z * v.z + v.w * v.w;
        }
        g_ee[t] = s;
    }
    if (t == 0) g_loss = 0.0f;
}

// ---------------------------------------------------------------------------
// Kernel 1: distances + argmin + fused epilogue
//   Thread (tx,ty)=(tid&15,tid>>4): 8-row x 4-code tile per 64-code chunk.
//   f32x2 packing along the ROW axis (row pairs adjacent in zs[d][m] so the
//   float4 shared load already delivers aligned register pairs).
//   __launch_bounds__(256,2): cap regs at 128 so 2 blocks/SM -> single wave.
// ---------------------------------------------------------------------------
__global__ __launch_bounds__(NTHR, 2)
void k_main(const float* __restrict__ z, const float* __restrict__ emb,
            float* __restrict__ out) {
    __shared__ __align__(16) unsigned char sm[49152];
    float* zs = reinterpret_cast<float*>(sm);            // [64][128] zs[d*128+m]
    float* es = reinterpret_cast<float*>(sm + 32768);    // [64][64]  es[d*64+k]
    u64*   smin = reinterpret_cast<u64*>(sm + 32768);    // alias es (after mainloop)
    int*   sidx = reinterpret_cast<int*>(sm + 32768 + BM * 8);
    float* lred = reinterpret_cast<float*>(sm);          // alias zs (very end)

    const int tid = threadIdx.x;
    const int tx  = tid & 15;
    const int ty  = tid >> 4;
    const int row0 = blockIdx.x * BM;

    // ---- load z tile transposed to zs[d][m]
    for (int i = tid; i < BM * 16; i += NTHR) {
        int m  = (i & 15) | ((i >> 8) << 4);
        int dq = (i >> 4) & 15;
        float4 v = *reinterpret_cast<const float4*>(z + (size_t)(row0 + m) * DIM + dq * 4);
        zs[(dq * 4 + 0) * BM + m] = v.x;
        zs[(dq * 4 + 1) * BM + m] = v.y;
        zs[(dq * 4 + 2) * BM + m] = v.z;
        zs[(dq * 4 + 3) * BM + m] = v.w;
    }

    float    best[8];
    unsigned bidx[8];
#pragma unroll
    for (int r = 0; r < 8; r++) { best[r] = 3.4e38f; bidx[r] = 0u; }

    for (int c = 0; c < NCHUNK; c++) {
        const int k0 = c * 64;
        __syncthreads();
        for (int i = tid; i < 64 * 16; i += NTHR) {
            int kk = (i & 15) | ((i >> 8) << 4);
            int dq = (i >> 4) & 15;
            float4 v = *reinterpret_cast<const float4*>(emb + (size_t)(k0 + kk) * DIM + dq * 4);
            es[(dq * 4 + 0) * 64 + kk] = v.x;
            es[(dq * 4 + 1) * 64 + kk] = v.y;
            es[(dq * 4 + 2) * 64 + kk] = v.z;
            es[(dq * 4 + 3) * 64 + kk] = v.w;
        }
        __syncthreads();

        // acc[j*4+p]: code tx*4+j, row pair (ty*8+2p, ty*8+2p+1)
        u64 acc[16];
#pragma unroll
        for (int i = 0; i < 16; i++) acc[i] = 0ULL;

        const float* zp_base = zs + ty * 8;
        const float* ep_base = es + tx * 4;
#pragma unroll 4
        for (int d = 0; d < DIM; d++) {
            float4 za = *reinterpret_cast<const float4*>(zp_base + d * BM);
            float4 zb = *reinterpret_cast<const float4*>(zp_base + d * BM + 4);
            float4 ef = *reinterpret_cast<const float4*>(ep_base + d * 64);
            u64 zp0 = pk(za.x, za.y), zp1 = pk(za.z, za.w);
            u64 zp2 = pk(zb.x, zb.y), zp3 = pk(zb.z, zb.w);
            u64 e0 = dup_f(ef.x), e1 = dup_f(ef.y), e2 = dup_f(ef.z), e3 = dup_f(ef.w);
            fma2(acc[0],  zp0, e0); fma2(acc[1],  zp1, e0);
            fma2(acc[2],  zp2, e0); fma2(acc[3],  zp3, e0);
            fma2(acc[4],  zp0, e1); fma2(acc[5],  zp1, e1);
            fma2(acc[6],  zp2, e1); fma2(acc[7],  zp3, e1);
            fma2(acc[8],  zp0, e2); fma2(acc[9],  zp1, e2);
            fma2(acc[10], zp2, e2); fma2(acc[11], zp3, e2);
            fma2(acc[12], zp0, e3); fma2(acc[13], zp1, e3);
            fma2(acc[14], zp2, e3); fma2(acc[15], zp3, e3);
        }

        // chunk epilogue: dist = ||e||^2 - 2*dot
        float eek[4];
#pragma unroll
        for (int j = 0; j < 4; j++) eek[j] = __ldg(&g_ee[k0 + tx * 4 + j]);
#pragma unroll
        for (int j = 0; j < 4; j++) {
#pragma unroll
            for (int p = 0; p < 4; p++) {
                float d0, d1;
                unpk(acc[j * 4 + p], d0, d1);
                float dist0 = fmaf(-2.0f, d0, eek[j]);
                float dist1 = fmaf(-2.0f, d1, eek[j]);
                unsigned kj = (unsigned)(k0 + tx * 4 + j);
                if (dist0 < best[2 * p])     { best[2 * p]     = dist0; bidx[2 * p]     = kj; }
                if (dist1 < best[2 * p + 1]) { best[2 * p + 1] = dist1; bidx[2 * p + 1] = kj; }
            }
        }
    }

    // ---- cross-thread argmin reduce per row (packed key, low-index tiebreak)
    __syncthreads();
    if (tid < BM) smin[tid] = 0xFFFFFFFFFFFFFFFFULL;
    __syncthreads();
#pragma unroll
    for (int r = 0; r < 8; r++) {
        unsigned u = __float_as_uint(best[r]);
        u = (u & 0x80000000u) ? ~u : (u | 0x80000000u);
        u64 key = ((u64)u << 32) | (u64)bidx[r];
        atomicMin(&smin[ty * 8 + r], key);
    }
    __syncthreads();

    if (tid < BM) {
        int idx = (int)(smin[tid] & 0xFFFFFFFFull);
        sidx[tid] = idx;
        int row = row0 + tid;
        out[O_IDX + row] = (float)idx;
        atomicAdd(&g_ni[idx], 1.0f);
    }
    __syncthreads();

    // ---- fused epilogue: quantized gather + transposed write + loss + dw scatter
    float lacc = 0.0f;
    for (int i = tid; i < BM * DIM; i += NTHR) {
        int m = i & (BM - 1);
        int d = i >> 7;
        int row = row0 + m;
        int idx = sidx[m];
        float zv = zs[d * BM + m];
        float q  = __ldg(&emb[(size_t)idx * DIM + d]);
        float diff = q - zv;
        lacc += diff * diff;
        int b  = row >> 10;
        int hw = row & 1023;
        out[O_QV + (((size_t)(b * DIM + d)) << 10) + hw] = zv + diff;
        atomicAdd(&g_dw[idx * DIM + d], zv);
    }

#pragma unroll
    for (int o = 16; o > 0; o >>= 1) lacc += __shfl_xor_sync(0xFFFFFFFFu, lacc, o);
    __syncthreads();
    if ((tid & 31) == 0) lred[tid >> 5] = lacc;
    __syncthreads();
    if (tid == 0) {
        float s = 0.0f;
#pragma unroll
        for (int w = 0; w < NTHR / 32; w++) s += lred[w];
        atomicAdd(&g_loss, s);
    }
}

// ---------------------------------------------------------------------------
// Kernel 2 (fused): smoothing + EMA + new embeddings.
//   64 blocks x 256 threads; each block redundantly reduces n over K (cheap,
//   deterministic). Vector LOADS only; EMB/EMA out offsets are odd -> scalar
//   stores (STG.128 to a 4B-aligned address traps).
// ---------------------------------------------------------------------------
__global__ __launch_bounds__(256)
void k_final(const float* __restrict__ cs, const float* __restrict__ ema,
             float* __restrict__ out) {
    __shared__ float red[8];
    const int tid = threadIdx.x;

    // block-redundant reduction of n = sum_k raw_k (fixed order -> deterministic)
    float part = 0.0f;
#pragma unroll
    for (int k = tid; k < KCODES; k += 256)
        part += cs[k] * 0.99f + g_ni[k] * 0.01f;
#pragma unroll
    for (int o = 16; o > 0; o >>= 1) part += __shfl_xor_sync(0xFFFFFFFFu, part, o);
    if ((tid & 31) == 0) red[tid >> 5] = part;
    __syncthreads();
    float n = 0.0f;
#pragma unroll
    for (int w = 0; w < 8; w++) n += red[w];

    if (blockIdx.x == 0 && tid == 0)
        out[O_LOSS] = 0.25f * g_loss / 2097152.0f;

    const int i0 = (blockIdx.x * 256 + tid) * 4;   // element base, < 65536
    const int k  = i0 >> 6;                         // same code for all 4 elems
    float raw = cs[k] * 0.99f + g_ni[k] * 0.01f;
    float smooth = (raw + 1e-5f) / (n + 1024.0f * 1e-5f) * n;
    if ((i0 & 63) == 0) out[O_CL + k] = smooth;

    float4 ev = *reinterpret_cast<const float4*>(ema + i0);
    float4 dv = *reinterpret_cast<const float4*>(g_dw + i0);
    float inv = 1.0f / smooth;
    float ne0 = ev.x * 0.99f + dv.x * 0.01f;
    float ne1 = ev.y * 0.99f + dv.y * 0.01f;
    float ne2 = ev.z * 0.99f + dv.z * 0.01f;
    float ne3 = ev.w * 0.99f + dv.w * 0.01f;
    // scalar stores: O_EMA / O_EMB are odd element offsets (4B-aligned only)
    out[O_EMA + i0 + 0] = ne0;  out[O_EMB + i0 + 0] = ne0 * inv;
    out[O_EMA + i0 + 1] = ne1;  out[O_EMB + i0 + 1] = ne1 * inv;
    out[O_EMA + i0 + 2] = ne2;  out[O_EMB + i0 + 2] = ne2 * inv;
    out[O_EMA + i0 + 3] = ne3;  out[O_EMB + i0 + 3] = ne3 * inv;
}

// ---------------------------------------------------------------------------
extern "C" void kernel_launch(void* const* d_in, const int* in_sizes, int n_in,
                              void* d_out, int out_size) {
    const float* z   = (const float*)d_in[0];
    const float* emb = (const float*)d_in[1];
    const float* cs  = (const float*)d_in[2];
    const float* ema = (const float*)d_in[3];
    float* out = (float*)d_out;

    k_init<<<64, 256>>>(emb);
    k_main<<<N_TOT / BM, NTHR>>>(z, emb, out);
    k_final<<<64, 256>>>(cs, ema, out);
}